// round 16
// baseline (speedup 1.0000x reference)
#include <cuda_runtime.h>
#include <cuda_fp16.h>
#include <math_constants.h>
#include <cstdint>
#include <cstddef>

#define BB 4
#define CCH 512
#define C8 64
#define HH 128
#define WW 128
#define HWV (HH*WW)

static const size_t NTOT = (size_t)BB * CCH * HWV;

// ---------------- scratch ----------------------------------------------------
__device__ __align__(16) __half g_qTa[BB*HWV*C8];           // [b][w][h][c]
__device__ __align__(16) __half g_qTb[BB*HWV*C8];           // [b][h][w][c]
__device__ __align__(16) __half g_kTa[BB*HWV*C8];           // [b][w][h][c]
__device__ __align__(16) __half g_kTb[BB*HWV*C8];           // [b][h][w][c]
__device__ __align__(16) __half g_vh [(size_t)BB*CCH*HWV];  // [b][c][h][w]
__device__ __align__(16) __half g_vT [(size_t)BB*HWV*CCH];  // [b][w][h][c]
__device__ __align__(16) __half g_eH [(size_t)BB*HWV*HH];   // [b][w][h][j]
__device__ __align__(16) __half g_eW [(size_t)BB*HWV*WW];   // [b][h][w][j]
__device__ __align__(16) __half g_s1h[(size_t)BB*CCH*HWV];  // [b][c][w][h]
__device__ __align__(16) __half g_s2h[(size_t)BB*CCH*HWV];  // [b][c][h][w]
// packed A: rows 0-511 Wv, 512-575 Wk, 576-639 Wq
__device__ __align__(16) __half g_wall[640*CCH];
__device__ float g_ball[640];

// ---------------- PTX helpers ------------------------------------------------
__device__ __forceinline__ uint32_t smem_u32(const void* p) {
    uint32_t a;
    asm("{ .reg .u64 t; cvta.to.shared.u64 t, %1; cvt.u32.u64 %0, t; }" : "=r"(a) : "l"(p));
    return a;
}
__device__ __forceinline__ uint32_t pkh(__half a, __half b) {
    __half2 t = __halves2half2(a, b);
    return *reinterpret_cast<uint32_t*>(&t);
}
__device__ __forceinline__ float fast_exp(float x) {
    float t = fmaxf(x * 1.44269504f, -126.0f);
    float fi = floorf(t);
    float f = t - fi;
    float p = 1.33335581e-3f;
    p = fmaf(p, f, 9.61817461e-3f);
    p = fmaf(p, f, 5.55041087e-2f);
    p = fmaf(p, f, 2.40226507e-1f);
    p = fmaf(p, f, 6.93147181e-1f);
    p = fmaf(p, f, 1.0f);
    return p * __int_as_float(((int)fi + 127) << 23);
}
#define LDMATRIX_X4(r0,r1,r2,r3,addr) \
    asm volatile("ldmatrix.sync.aligned.m8n8.x4.shared.b16 {%0,%1,%2,%3}, [%4];" \
                 : "=r"(r0),"=r"(r1),"=r"(r2),"=r"(r3) : "r"(addr))
#define LDMATRIX_X4_T(r0,r1,r2,r3,addr) \
    asm volatile("ldmatrix.sync.aligned.m8n8.x4.trans.shared.b16 {%0,%1,%2,%3}, [%4];" \
                 : "=r"(r0),"=r"(r1),"=r"(r2),"=r"(r3) : "r"(addr))
#define MMA16816(d,a0,a1,a2,a3,b0,b1) \
    asm volatile("mma.sync.aligned.m16n8k16.row.col.f32.f16.f16.f32 " \
                 "{%0,%1,%2,%3},{%4,%5,%6,%7},{%8,%9},{%0,%1,%2,%3};" \
                 : "+f"((d)[0]),"+f"((d)[1]),"+f"((d)[2]),"+f"((d)[3]) \
                 : "r"(a0),"r"(a1),"r"(a2),"r"(a3),"r"(b0),"r"(b1))
#define CP_ASYNC16(dst,src) \
    asm volatile("cp.async.cg.shared.global [%0], [%1], 16;" :: "r"(dst),"l"(src))
#define CP_COMMIT() asm volatile("cp.async.commit_group;" ::: "memory")
#define CP_WAIT1()  asm volatile("cp.async.wait_group 1;" ::: "memory")
#define CP_WAIT0()  asm volatile("cp.async.wait_group 0;" ::: "memory")

#define LDR 80
#define LDB 272
#define LDT 272
#define PTA 144

// ---------------- merged weight/bias prep ------------------------------------
__global__ void prep_kernel(const float* __restrict__ Wq,
                            const float* __restrict__ Wv,
                            const float* __restrict__ Wk,
                            const float* __restrict__ bv,
                            const float* __restrict__ bk,
                            const float* __restrict__ bq) {
    int i = blockIdx.x * 256 + threadIdx.x;
    if (i < 512 * CCH) { g_wall[i] = __float2half_rn(Wv[i]); return; }
    i -= 512 * CCH;
    if (i < 64 * CCH) { g_wall[512 * CCH + i] = __float2half_rn(Wk[i]); return; }
    i -= 64 * CCH;
    if (i < 64 * CCH) { g_wall[576 * CCH + i] = __float2half_rn(Wq[i]); return; }
    i -= 64 * CCH;
    if (i < 640) {
        float v;
        if (i < 512) v = bv[i];
        else if (i < 576) v = bk[i - 512];
        else v = bq[i - 576];
        g_ball[i] = v;
    }
}
#define PREP_N (640*CCH + 640)

// ---------------- merged GEMM: 3-stage pipeline @ 2 CTA/SM --------------------
#define GA_A    0          // 3 x 10240 = 30720
#define GA_STG  30720      // 3 x 16384 = 49152
#define GA_BH   79872      // 2 x 8704  = 17408
#define GA_SM   97280

__global__ void __launch_bounds__(256) gemm_all_kernel(
    const float* __restrict__ Xe, const float* __restrict__ Xq)
{
    extern __shared__ char smem[];
    uint32_t sbase = smem_u32(smem);
    int tid = threadIdx.x, wid = tid >> 5, lane = tid & 31;
    int mt = blockIdx.x;
    int n0 = blockIdx.y * 128, b = blockIdx.z;
    int hfix = blockIdx.y;
    const float* X = (mt == 5) ? Xq : Xe;
    const float* Xb = X + (size_t)b * CCH * HWV + n0;
    int lg = lane >> 3, lr = lane & 7;

    if (mt < 4) {
        int m0 = mt * 128;
        int wm = wid & 3, wn = wid >> 2;
        const __half* Ahb = g_wall + (size_t)m0 * CCH;

        float acc[2][8][4];
#pragma unroll
        for (int i = 0; i < 2; i++)
#pragma unroll
            for (int j = 0; j < 8; j++)
#pragma unroll
                for (int k = 0; k < 4; k++) acc[i][j][k] = 0.f;

        auto issue = [&](int c, int sb) {
            int kc0 = c * 32;
#pragma unroll
            for (int i = 0; i < 2; i++) {
                int idx = i * 256 + tid;
                int r = idx >> 2, seg = idx & 3;
                CP_ASYNC16(sbase + GA_A + sb * 10240 + r * LDR + seg * 16,
                           Ahb + (size_t)r * CCH + kc0 + seg * 8);
            }
#pragma unroll
            for (int i = 0; i < 4; i++) {
                int idx = i * 256 + tid;
                int r = idx >> 5, seg = idx & 31;
                CP_ASYNC16(sbase + GA_STG + sb * 16384 + r * 512 + seg * 16,
                           Xb + (size_t)(kc0 + r) * HWV + seg * 4);
            }
            CP_COMMIT();
        };

        issue(0, 0); issue(1, 1);
        for (int c = 0; c < 16; c++) {
            int sb = c % 3, hb = c & 1;
            if (c < 15) CP_WAIT1(); else CP_WAIT0();
            {
                const char* stg = smem + GA_STG + sb * 16384;
                char* bh = smem + GA_BH + hb * 8704;
#pragma unroll
                for (int i = 0; i < 4; i++) {
                    int idx = i * 256 + tid;
                    int r = idx >> 5, cc = idx & 31;
                    float4 f = *(const float4*)(stg + r * 512 + cc * 16);
                    uint2 hv = make_uint2(
                        pkh(__float2half_rn(f.x), __float2half_rn(f.y)),
                        pkh(__float2half_rn(f.z), __float2half_rn(f.w)));
                    *(uint2*)(bh + r * LDB + cc * 8) = hv;
                }
            }
            __syncthreads();
            if (c < 14) issue(c + 2, (c + 2) % 3);

            uint32_t sA = sbase + GA_A + sb * 10240;
            uint32_t sBH = sbase + GA_BH + hb * 8704;
#pragma unroll
            for (int ks = 0; ks < 2; ks++) {
                uint32_t ah[2][4];
#pragma unroll
                for (int mf = 0; mf < 2; mf++) {
                    uint32_t roff = (wm * 32 + mf * 16 + lr + (lg & 1) * 8) * LDR
                                  + (ks * 16 + (lg >> 1) * 8) * 2;
                    LDMATRIX_X4(ah[mf][0], ah[mf][1], ah[mf][2], ah[mf][3], sA + roff);
                }
                uint32_t trow = ks * 16 + ((lane >> 3) & 1) * 8 + lr;
                uint32_t bh[8][2];
#pragma unroll
                for (int np = 0; np < 4; np++) {
                    uint32_t tcol = wn * 64 + np * 16 + ((lane >> 4) & 1) * 8;
                    uint32_t r0, r1, r2, r3;
                    LDMATRIX_X4_T(r0, r1, r2, r3, sBH + trow * LDB + tcol * 2);
                    bh[np * 2][0] = r0; bh[np * 2][1] = r1;
                    bh[np * 2 + 1][0] = r2; bh[np * 2 + 1][1] = r3;
                }
#pragma unroll
                for (int mf = 0; mf < 2; mf++)
#pragma unroll
                    for (int nf = 0; nf < 8; nf++)
                        MMA16816(acc[mf][nf], ah[mf][0], ah[mf][1], ah[mf][2], ah[mf][3],
                                 bh[nf][0], bh[nf][1]);
            }
            __syncthreads();
        }

        char* st = smem;
#pragma unroll
        for (int mf = 0; mf < 2; mf++) {
            int row_l = wm * 32 + mf * 16 + (lane >> 2);
            int row = m0 + row_l;
            float bv0 = g_ball[row], bv1 = g_ball[row + 8];
            __half* op0 = g_vh + (size_t)b * CCH * HWV + (size_t)row * HWV
                        + n0 + wn * 64 + (lane & 3) * 2;
            __half* op1 = op0 + (size_t)8 * HWV;
#pragma unroll
            for (int nf = 0; nf < 8; nf++) {
                int n = wn * 64 + nf * 8 + (lane & 3) * 2;
                __half h00 = __float2half_rn(acc[mf][nf][0] + bv0);
                __half h01 = __float2half_rn(acc[mf][nf][1] + bv0);
                __half h10 = __float2half_rn(acc[mf][nf][2] + bv1);
                __half h11 = __float2half_rn(acc[mf][nf][3] + bv1);
                *(__half2*)(op0 + nf * 8) = __halves2half2(h00, h01);
                *(__half2*)(op1 + nf * 8) = __halves2half2(h10, h11);
                *(__half*)(st + n * 272 + row_l * 2)             = h00;
                *(__half*)(st + (n + 1) * 272 + row_l * 2)       = h01;
                *(__half*)(st + n * 272 + (row_l + 8) * 2)       = h10;
                *(__half*)(st + (n + 1) * 272 + (row_l + 8) * 2) = h11;
            }
        }
        __syncthreads();
#pragma unroll
        for (int i = 0; i < 8; i++) {
            int idx = i * 256 + tid;
            int w = idx >> 4, seg = idx & 15;
            *(uint4*)(g_vT + ((((size_t)b * WW + w) * HH + hfix) * CCH) + mt * 128 + seg * 8)
                = *(const uint4*)(st + w * 272 + seg * 16);
        }
    } else {
        int m0 = 512 + (mt - 4) * 64;
        int wm = wid & 1, wn = wid >> 1;
        const __half* Ahb = g_wall + (size_t)m0 * CCH;

        float acc[2][4][4];
#pragma unroll
        for (int i = 0; i < 2; i++)
#pragma unroll
            for (int j = 0; j < 4; j++)
#pragma unroll
                for (int k = 0; k < 4; k++) acc[i][j][k] = 0.f;

        auto issue = [&](int c, int sb) {
            int kc0 = c * 32;
            {
                int r = tid >> 2, seg = tid & 3;
                CP_ASYNC16(sbase + GA_A + sb * 10240 + r * LDR + seg * 16,
                           Ahb + (size_t)r * CCH + kc0 + seg * 8);
            }
#pragma unroll
            for (int i = 0; i < 4; i++) {
                int idx = i * 256 + tid;
                int r = idx >> 5, seg = idx & 31;
                CP_ASYNC16(sbase + GA_STG + sb * 16384 + r * 512 + seg * 16,
                           Xb + (size_t)(kc0 + r) * HWV + seg * 4);
            }
            CP_COMMIT();
        };

        issue(0, 0); issue(1, 1);
        for (int c = 0; c < 16; c++) {
            int sb = c % 3, hb = c & 1;
            if (c < 15) CP_WAIT1(); else CP_WAIT0();
            {
                const char* stg = smem + GA_STG + sb * 16384;
                char* bh = smem + GA_BH + hb * 8704;
#pragma unroll
                for (int i = 0; i < 4; i++) {
                    int idx = i * 256 + tid;
                    int r = idx >> 5, cc = idx & 31;
                    float4 f = *(const float4*)(stg + r * 512 + cc * 16);
                    uint2 hv = make_uint2(
                        pkh(__float2half_rn(f.x), __float2half_rn(f.y)),
                        pkh(__float2half_rn(f.z), __float2half_rn(f.w)));
                    *(uint2*)(bh + r * LDB + cc * 8) = hv;
                }
            }
            __syncthreads();
            if (c < 14) issue(c + 2, (c + 2) % 3);

            uint32_t sA = sbase + GA_A + sb * 10240;
            uint32_t sBH = sbase + GA_BH + hb * 8704;
#pragma unroll
            for (int ks = 0; ks < 2; ks++) {
                uint32_t ah[2][4];
#pragma unroll
                for (int mf = 0; mf < 2; mf++) {
                    uint32_t roff = (wm * 32 + mf * 16 + lr + (lg & 1) * 8) * LDR
                                  + (ks * 16 + (lg >> 1) * 8) * 2;
                    LDMATRIX_X4(ah[mf][0], ah[mf][1], ah[mf][2], ah[mf][3], sA + roff);
                }
                uint32_t trow = ks * 16 + ((lane >> 3) & 1) * 8 + lr;
                uint32_t bh[4][2];
#pragma unroll
                for (int np = 0; np < 2; np++) {
                    uint32_t tcol = wn * 32 + np * 16 + ((lane >> 4) & 1) * 8;
                    uint32_t r0, r1, r2, r3;
                    LDMATRIX_X4_T(r0, r1, r2, r3, sBH + trow * LDB + tcol * 2);
                    bh[np * 2][0] = r0; bh[np * 2][1] = r1;
                    bh[np * 2 + 1][0] = r2; bh[np * 2 + 1][1] = r3;
                }
#pragma unroll
                for (int mf = 0; mf < 2; mf++)
#pragma unroll
                    for (int nf = 0; nf < 4; nf++)
                        MMA16816(acc[mf][nf], ah[mf][0], ah[mf][1], ah[mf][2], ah[mf][3],
                                 bh[nf][0], bh[nf][1]);
            }
            __syncthreads();
        }

        char* st = smem;
#pragma unroll
        for (int mf = 0; mf < 2; mf++) {
            int row_l = wm * 32 + mf * 16 + (lane >> 2);
            float bv0 = g_ball[m0 + row_l], bv1 = g_ball[m0 + row_l + 8];
#pragma unroll
            for (int nf = 0; nf < 4; nf++) {
                int n = wn * 32 + nf * 8 + (lane & 3) * 2;
                *(__half*)(st + n * PTA + row_l * 2)             = __float2half_rn(acc[mf][nf][0] + bv0);
                *(__half*)(st + (n + 1) * PTA + row_l * 2)       = __float2half_rn(acc[mf][nf][1] + bv0);
                *(__half*)(st + n * PTA + (row_l + 8) * 2)       = __float2half_rn(acc[mf][nf][2] + bv1);
                *(__half*)(st + (n + 1) * PTA + (row_l + 8) * 2) = __float2half_rn(acc[mf][nf][3] + bv1);
            }
        }
        __syncthreads();
        __half* ta = (mt == 4) ? g_kTa : g_qTa;
        __half* tb = (mt == 4) ? g_kTb : g_qTb;
#pragma unroll
        for (int i = 0; i < 4; i++) {
            int idx = i * 256 + tid;
            int w = idx >> 3, seg = idx & 7;
            uint4 v = *(const uint4*)(st + w * PTA + seg * 16);
            *(uint4*)(ta + (((size_t)b * WW + w) * HH + hfix) * C8 + seg * 8) = v;
            *(uint4*)(tb + (((size_t)b * HH + hfix) * WW + w) * C8 + seg * 8) = v;
        }
    }
}

// ---------------- merged energy kernel ----------------------------------------
__global__ void __launch_bounds__(256) energy_all_kernel() {
    __shared__ __align__(16) char smh[2 * 128 * PTA];
    uint32_t sA = smem_u32(smh);
    uint32_t sB = sA + 128 * PTA;
    int tid = threadIdx.x, wid = tid >> 5, lane = tid & 31;
    int f = blockIdx.x, b = blockIdx.y;
    bool isH = (blockIdx.z == 0);
    int wm = wid & 3, wn = wid >> 2;

    const __half* qsrc;
    const __half* ksrc;
    __half* obase;
    if (isH) {
        qsrc = g_qTa + ((size_t)(b * WW + f)) * HH * C8;
        ksrc = g_kTa + ((size_t)(b * WW + f)) * HH * C8;
        obase = g_eH + (((size_t)b * WW + f) * HH) * 128;
    } else {
        qsrc = g_qTb + ((size_t)(b * HH + f)) * WW * C8;
        ksrc = g_kTb + ((size_t)(b * HH + f)) * WW * C8;
        obase = g_eW + (((size_t)b * HH + f) * WW) * 128;
    }
#pragma unroll
    for (int i = 0; i < 4; i++) {
        int idx = i * 256 + tid;
        int r = idx >> 3, seg = idx & 7;
        CP_ASYNC16(sA + r * PTA + seg * 16, qsrc + (size_t)r * C8 + seg * 8);
        CP_ASYNC16(sB + r * PTA + seg * 16, ksrc + (size_t)r * C8 + seg * 8);
    }
    CP_COMMIT(); CP_WAIT0();
    __syncthreads();

    float acc[2][8][4];
#pragma unroll
    for (int i = 0; i < 2; i++)
#pragma unroll
        for (int j = 0; j < 8; j++)
#pragma unroll
            for (int k = 0; k < 4; k++) acc[i][j][k] = 0.f;

    int lg = lane >> 3, lr = lane & 7;
#pragma unroll
    for (int kk = 0; kk < 4; kk++) {
        uint32_t a[2][4];
#pragma unroll
        for (int mf = 0; mf < 2; mf++) {
            uint32_t roff = (wm * 32 + mf * 16 + lr + (lg & 1) * 8) * PTA
                          + (kk * 16 + (lg >> 1) * 8) * 2;
            LDMATRIX_X4(a[mf][0], a[mf][1], a[mf][2], a[mf][3], sA + roff);
        }
        uint32_t bf[8][2];
#pragma unroll
        for (int np = 0; np < 4; np++) {
            uint32_t roff = (wn * 64 + np * 16 + (lg >> 1) * 8 + lr) * PTA
                          + (kk * 16 + (lg & 1) * 8) * 2;
            uint32_t r0, r1, r2, r3;
            LDMATRIX_X4(r0, r1, r2, r3, sB + roff);
            bf[np * 2][0] = r0; bf[np * 2][1] = r1;
            bf[np * 2 + 1][0] = r2; bf[np * 2 + 1][1] = r3;
        }
#pragma unroll
        for (int mf = 0; mf < 2; mf++)
#pragma unroll
            for (int nf = 0; nf < 8; nf++)
                MMA16816(acc[mf][nf], a[mf][0], a[mf][1], a[mf][2], a[mf][3],
                         bf[nf][0], bf[nf][1]);
    }
#pragma unroll
    for (int mf = 0; mf < 2; mf++) {
        int m0 = wm * 32 + mf * 16 + (lane >> 2);
        int m1 = m0 + 8;
#pragma unroll
        for (int nf = 0; nf < 8; nf++) {
            int j0 = wn * 64 + nf * 8 + (lane & 3) * 2;
            float v00 = acc[mf][nf][0], v01 = acc[mf][nf][1];
            float v10 = acc[mf][nf][2], v11 = acc[mf][nf][3];
            if (isH) {
                if (j0 == m0)     v00 = -30000.f;
                if (j0 + 1 == m0) v01 = -30000.f;
                if (j0 == m1)     v10 = -30000.f;
                if (j0 + 1 == m1) v11 = -30000.f;
            }
            *(__half2*)(obase + (size_t)m0 * 128 + j0) = __floats2half2_rn(v00, v01);
            *(__half2*)(obase + (size_t)m1 * 128 + j0) = __floats2half2_rn(v10, v11);
        }
    }
}

// ---------------- single-pass softmax ------------------------------------------
__global__ void softmax_apply_kernel() {
    int row  = blockIdx.x * 8 + (threadIdx.x >> 5);
    int lane = threadIdx.x & 31;
    int b = row >> 14, h = (row >> 7) & 127, w = row & 127;
    __half* pH = g_eH + (((size_t)b * WW + w) * HH + h) * 128;
    __half* pW = g_eW + (size_t)row * 128;
    float v[8];
    float m = -CUDART_INF_F;
#pragma unroll
    for (int i = 0; i < 4; i++) { v[i] = __half2float(pH[lane + 32 * i]); m = fmaxf(m, v[i]); }
#pragma unroll
    for (int i = 4; i < 8; i++) { v[i] = __half2float(pW[lane + 32 * (i - 4)]); m = fmaxf(m, v[i]); }
#pragma unroll
    for (int o = 16; o > 0; o >>= 1) m = fmaxf(m, __shfl_xor_sync(0xffffffffu, m, o));
    float s = 0.f;
#pragma unroll
    for (int i = 0; i < 8; i++) { v[i] = fast_exp(v[i] - m); s += v[i]; }
#pragma unroll
    for (int o = 16; o > 0; o >>= 1) s += __shfl_xor_sync(0xffffffffu, s, o);
    float inv = 1.0f / s;
#pragma unroll
    for (int i = 0; i < 4; i++) pH[lane + 32 * i] = __float2half(v[i] * inv);
#pragma unroll
    for (int i = 4; i < 8; i++) pW[lane + 32 * (i - 4)] = __float2half(v[i] * inv);
}

// ---------------- attn out: one (ct, isH) tile per block ----------------------
#define AT_A   0
#define AT_B   34816
#define AT_SM  69632

__global__ void __launch_bounds__(256) attn_all_kernel() {
    extern __shared__ char smem[];
    uint32_t sbase = smem_u32(smem);
    int tid = threadIdx.x, wid = tid >> 5, lane = tid & 31;
    int zz = blockIdx.x;
    int ct = zz >> 1;
    bool isH = (zz & 1) == 0;
    int f = blockIdx.y, b = blockIdx.z;
    int wm = wid & 3, wn = wid >> 2;

    const __half* Ab;
    const __half* Bm;
    __half* out;
    if (isH) {
        Ab = g_vT + ((size_t)(b * WW + f)) * HH * CCH;
        out = g_s1h; Bm = g_eH;
    } else {
        Ab = g_vh + (size_t)b * CCH * HWV + (size_t)f * WW;
        out = g_s2h; Bm = g_eW;
    }
    const __half* Bc = Bm + ((size_t)b * 128 + f) * 16384;

#pragma unroll
    for (int i = 0; i < 8; i++) {
        int idx = i * 256 + tid;
        int r = idx >> 4, seg = idx & 15;
        const __half* srcA = isH
            ? Ab + (size_t)r * CCH + ct * 128 + seg * 8
            : Ab + (size_t)(ct * 128 + r) * HWV + seg * 8;
        CP_ASYNC16(sbase + AT_A + r * LDT + seg * 16, srcA);
        CP_ASYNC16(sbase + AT_B + r * LDT + seg * 16, Bc + (size_t)r * 128 + seg * 8);
    }
    CP_COMMIT(); CP_WAIT0();
    __syncthreads();

    int lg = lane >> 3, lr = lane & 7;
    uint32_t sB = sbase + AT_B;
    uint32_t sA = sbase + AT_A;

    float acc[2][8][4];
#pragma unroll
    for (int i = 0; i < 2; i++)
#pragma unroll
        for (int j = 0; j < 8; j++)
#pragma unroll
            for (int k = 0; k < 4; k++) acc[i][j][k] = 0.f;

#pragma unroll
    for (int kk = 0; kk < 8; kk++) {
        uint32_t a[2][4];
        if (isH) {
#pragma unroll
            for (int mf = 0; mf < 2; mf++) {
                uint32_t krow = kk * 16 + ((lane >> 4) & 1) * 8 + lr;
                uint32_t mcol = wm * 32 + mf * 16 + ((lane >> 3) & 1) * 8;
                LDMATRIX_X4_T(a[mf][0], a[mf][1], a[mf][2], a[mf][3],
                              sA + krow * LDT + mcol * 2);
            }
        } else {
#pragma unroll
            for (int mf = 0; mf < 2; mf++) {
                uint32_t roff = (wm * 32 + mf * 16 + lr + (lg & 1) * 8) * LDT
                              + (kk * 16 + (lg >> 1) * 8) * 2;
                LDMATRIX_X4(a[mf][0], a[mf][1], a[mf][2], a[mf][3], sA + roff);
            }
        }
        uint32_t bf[8][2];
#pragma unroll
        for (int np = 0; np < 4; np++) {
            uint32_t roff = (wn * 64 + np * 16 + (lg >> 1) * 8 + lr) * LDT
                          + (kk * 16 + (lg & 1) * 8) * 2;
            uint32_t r0, r1, r2, r3;
            LDMATRIX_X4(r0, r1, r2, r3, sB + roff);
            bf[np * 2][0] = r0; bf[np * 2][1] = r1;
            bf[np * 2 + 1][0] = r2; bf[np * 2 + 1][1] = r3;
        }
#pragma unroll
        for (int mf = 0; mf < 2; mf++)
#pragma unroll
            for (int nf = 0; nf < 8; nf++)
                MMA16816(acc[mf][nf], a[mf][0], a[mf][1], a[mf][2], a[mf][3],
                         bf[nf][0], bf[nf][1]);
    }

    __half* oc = out + (size_t)b * CCH * HWV + (size_t)f * 128
               + (size_t)ct * 128 * HWV;
#pragma unroll
    for (int mf = 0; mf < 2; mf++) {
        int row = wm * 32 + mf * 16 + (lane >> 2);
        __half* op0 = oc + (size_t)row * HWV + wn * 64 + (lane & 3) * 2;
        __half* op1 = op0 + (size_t)8 * HWV;
#pragma unroll
        for (int nf = 0; nf < 8; nf++) {
            *(__half2*)(op0 + nf * 8) = __floats2half2_rn(acc[mf][nf][0], acc[mf][nf][1]);
            *(__half2*)(op1 + nf * 8) = __floats2half2_rn(acc[mf][nf][2], acc[mf][nf][3]);
        }
    }
}

// ---------------- combine (64x64 half2 tiles) ---------------------------------
__global__ void combine_kernel(float* __restrict__ out,
                               const float* __restrict__ xe,
                               const float* __restrict__ xq,
                               const float* __restrict__ g1p,
                               const float* __restrict__ g2p) {
    __shared__ __half2 sm[64][33];
    int bc = blockIdx.z;
    int w0 = blockIdx.x * 64, h0 = blockIdx.y * 64;
    int tx = threadIdx.x, ty = threadIdx.y;
    size_t base = (size_t)bc * HWV;
    const __half* s1 = g_s1h + base;
#pragma unroll
    for (int r = 0; r < 4; r++) {
        int wp = ty + r * 8;
        int w = w0 + 2 * wp;
        __half2 a = *(const __half2*)(s1 + (size_t)w * HH + h0 + 2 * tx);
        __half2 bq2 = *(const __half2*)(s1 + (size_t)(w + 1) * HH + h0 + 2 * tx);
        sm[2 * tx][wp]     = __halves2half2(__low2half(a),  __low2half(bq2));
        sm[2 * tx + 1][wp] = __halves2half2(__high2half(a), __high2half(bq2));
    }
    __syncthreads();
    float gam1 = g1p[0], gam2 = g2p[0];
#pragma unroll
    for (int r = 0; r < 8; r++) {
        int hl = ty + r * 8;
        int h = h0 + hl;
        size_t idx = base + (size_t)h * WW + w0 + 2 * tx;
        __half2 s1v = sm[hl][tx];
        __half2 s2v = *(const __half2*)(g_s2h + idx);
        float t0 = __low2float(s1v)  + __low2float(s2v)  + 2.0f;
        float t1 = __high2float(s1v) + __high2float(s2v) + 2.0f;
        float2 xev = *(const float2*)(xe + idx);
        float2 xqv = *(const float2*)(xq + idx);
        *(float2*)(out + idx) = make_float2(fmaf(gam1, t0, xev.x), fmaf(gam1, t1, xev.y));
        *(float2*)(out + NTOT + idx) = make_float2(fmaf(gam2, t0, xqv.x), fmaf(gam2, t1, xqv.y));
    }
}

// ---------------- launch ---------------------------------------------------------
extern "C" void kernel_launch(void* const* d_in, const int* in_sizes, int n_in,
                              void* d_out, int out_size) {
    const float* xe = (const float*)d_in[0];
    const float* xq = (const float*)d_in[1];
    const float* Wq = (const float*)d_in[2];
    const float* bq = (const float*)d_in[3];
    const float* Wk = (const float*)d_in[4];
    const float* bk = (const float*)d_in[5];
    const float* Wv = (const float*)d_in[6];
    const float* bv = (const float*)d_in[7];
    const float* g1 = (const float*)d_in[8];
    const float* g2 = (const float*)d_in[9];
    float* out = (float*)d_out;

    cudaFuncSetAttribute(gemm_all_kernel,
                         cudaFuncAttributeMaxDynamicSharedMemorySize, GA_SM);
    cudaFuncSetAttribute(attn_all_kernel,
                         cudaFuncAttributeMaxDynamicSharedMemorySize, AT_SM);

    // 1. weight/bias prep
    prep_kernel<<<(PREP_N + 255) / 256, 256>>>(Wq, Wv, Wk, bv, bk, bq);

    // 2. projections: 3-stage cp.async pipeline at 2 CTAs/SM
    gemm_all_kernel<<<dim3(6, HWV / 128, BB), 256, GA_SM>>>(xe, xq);

    // 3. both energies
    energy_all_kernel<<<dim3(128, BB, 2), 256>>>();

    // 4. single-pass softmax
    softmax_apply_kernel<<<(BB * HH * WW) / 8, 256>>>();

    // 5. attention outputs (one (ct, H/W) tile per block)
    attn_all_kernel<<<dim3(8, 128, BB), 256, AT_SM>>>();

    // 6. combine
    combine_kernel<<<dim3(2, 2, BB * CCH), dim3(32, 8)>>>(out, xe, xq, g1, g2);
}

// round 17
// speedup vs baseline: 1.0202x; 1.0202x over previous
#include <cuda_runtime.h>
#include <cuda_fp16.h>
#include <math_constants.h>
#include <cstdint>
#include <cstddef>

#define BB 4
#define CCH 512
#define C8 64
#define HH 128
#define WW 128
#define HWV (HH*WW)

static const size_t NTOT = (size_t)BB * CCH * HWV;

// ---------------- scratch ----------------------------------------------------
__device__ __align__(16) __half g_qTa[BB*HWV*C8];           // [b][w][h][c]
__device__ __align__(16) __half g_qTb[BB*HWV*C8];           // [b][h][w][c]
__device__ __align__(16) __half g_kTa[BB*HWV*C8];           // [b][w][h][c]
__device__ __align__(16) __half g_kTb[BB*HWV*C8];           // [b][h][w][c]
__device__ __align__(16) __half g_vh [(size_t)BB*CCH*HWV];  // [b][c][h][w]
__device__ __align__(16) __half g_vT [(size_t)BB*HWV*CCH];  // [b][w][h][c]
__device__ __align__(16) __half g_eH [(size_t)BB*HWV*HH];   // [b][w][h][j]
__device__ __align__(16) __half g_eW [(size_t)BB*HWV*WW];   // [b][h][w][j]
__device__ __align__(16) __half g_s1h[(size_t)BB*CCH*HWV];  // [b][c][w][h]
__device__ __align__(16) __half g_s2h[(size_t)BB*CCH*HWV];  // [b][c][h][w]
// packed A: rows 0-511 Wv, 512-575 Wk, 576-639 Wq
__device__ __align__(16) __half g_wall[640*CCH];
__device__ float g_ball[640];

// ---------------- PTX helpers ------------------------------------------------
__device__ __forceinline__ uint32_t smem_u32(const void* p) {
    uint32_t a;
    asm("{ .reg .u64 t; cvta.to.shared.u64 t, %1; cvt.u32.u64 %0, t; }" : "=r"(a) : "l"(p));
    return a;
}
__device__ __forceinline__ uint32_t pkh(__half a, __half b) {
    __half2 t = __halves2half2(a, b);
    return *reinterpret_cast<uint32_t*>(&t);
}
__device__ __forceinline__ float fast_exp(float x) {
    float t = fmaxf(x * 1.44269504f, -126.0f);
    float fi = floorf(t);
    float f = t - fi;
    float p = 1.33335581e-3f;
    p = fmaf(p, f, 9.61817461e-3f);
    p = fmaf(p, f, 5.55041087e-2f);
    p = fmaf(p, f, 2.40226507e-1f);
    p = fmaf(p, f, 6.93147181e-1f);
    p = fmaf(p, f, 1.0f);
    return p * __int_as_float(((int)fi + 127) << 23);
}
#define LDMATRIX_X4(r0,r1,r2,r3,addr) \
    asm volatile("ldmatrix.sync.aligned.m8n8.x4.shared.b16 {%0,%1,%2,%3}, [%4];" \
                 : "=r"(r0),"=r"(r1),"=r"(r2),"=r"(r3) : "r"(addr))
#define LDMATRIX_X4_T(r0,r1,r2,r3,addr) \
    asm volatile("ldmatrix.sync.aligned.m8n8.x4.trans.shared.b16 {%0,%1,%2,%3}, [%4];" \
                 : "=r"(r0),"=r"(r1),"=r"(r2),"=r"(r3) : "r"(addr))
#define MMA16816(d,a0,a1,a2,a3,b0,b1) \
    asm volatile("mma.sync.aligned.m16n8k16.row.col.f32.f16.f16.f32 " \
                 "{%0,%1,%2,%3},{%4,%5,%6,%7},{%8,%9},{%0,%1,%2,%3};" \
                 : "+f"((d)[0]),"+f"((d)[1]),"+f"((d)[2]),"+f"((d)[3]) \
                 : "r"(a0),"r"(a1),"r"(a2),"r"(a3),"r"(b0),"r"(b1))
#define CP_ASYNC16(dst,src) \
    asm volatile("cp.async.cg.shared.global [%0], [%1], 16;" :: "r"(dst),"l"(src))
#define CP_COMMIT() asm volatile("cp.async.commit_group;" ::: "memory")
#define CP_WAIT1()  asm volatile("cp.async.wait_group 1;" ::: "memory")
#define CP_WAIT0()  asm volatile("cp.async.wait_group 0;" ::: "memory")

#define LDR 80
#define LDB 272
#define LDT 272
#define PTA 144

// ---------------- merged weight/bias prep ------------------------------------
__global__ void prep_kernel(const float* __restrict__ Wq,
                            const float* __restrict__ Wv,
                            const float* __restrict__ Wk,
                            const float* __restrict__ bv,
                            const float* __restrict__ bk,
                            const float* __restrict__ bq) {
    int i = blockIdx.x * 256 + threadIdx.x;
    if (i < 512 * CCH) { g_wall[i] = __float2half_rn(Wv[i]); return; }
    i -= 512 * CCH;
    if (i < 64 * CCH) { g_wall[512 * CCH + i] = __float2half_rn(Wk[i]); return; }
    i -= 64 * CCH;
    if (i < 64 * CCH) { g_wall[576 * CCH + i] = __float2half_rn(Wq[i]); return; }
    i -= 64 * CCH;
    if (i < 640) {
        float v;
        if (i < 512) v = bv[i];
        else if (i < 576) v = bk[i - 512];
        else v = bq[i - 576];
        g_ball[i] = v;
    }
}
#define PREP_N (640*CCH + 640)

// ---------------- merged GEMM (2-stage, 70.6KB -> 2 CTA/SM) -------------------
#define GA_A    0          // 2 x 10240
#define GA_STG  20480      // 2 x 16384
#define GA_BH   53248      // 2 x 8704
#define GA_SM   70656

__global__ void __launch_bounds__(256) gemm_all_kernel(
    const float* __restrict__ Xe, const float* __restrict__ Xq)
{
    extern __shared__ char smem[];
    uint32_t sbase = smem_u32(smem);
    int tid = threadIdx.x, wid = tid >> 5, lane = tid & 31;
    int mt = blockIdx.x;
    int n0 = blockIdx.y * 128, b = blockIdx.z;
    int hfix = blockIdx.y;
    const float* X = (mt == 5) ? Xq : Xe;
    const float* Xb = X + (size_t)b * CCH * HWV + n0;
    int lg = lane >> 3, lr = lane & 7;

    if (mt < 4) {
        int m0 = mt * 128;
        int wm = wid & 3, wn = wid >> 2;
        const __half* Ahb = g_wall + (size_t)m0 * CCH;

        float acc[2][8][4];
#pragma unroll
        for (int i = 0; i < 2; i++)
#pragma unroll
            for (int j = 0; j < 8; j++)
#pragma unroll
                for (int k = 0; k < 4; k++) acc[i][j][k] = 0.f;

        auto issue = [&](int c, int sb) {
            int kc0 = c * 32;
#pragma unroll
            for (int i = 0; i < 2; i++) {
                int idx = i * 256 + tid;
                int r = idx >> 2, seg = idx & 3;
                CP_ASYNC16(sbase + GA_A + sb * 10240 + r * LDR + seg * 16,
                           Ahb + (size_t)r * CCH + kc0 + seg * 8);
            }
#pragma unroll
            for (int i = 0; i < 4; i++) {
                int idx = i * 256 + tid;
                int r = idx >> 5, seg = idx & 31;
                CP_ASYNC16(sbase + GA_STG + sb * 16384 + r * 512 + seg * 16,
                           Xb + (size_t)(kc0 + r) * HWV + seg * 4);
            }
            CP_COMMIT();
        };

        issue(0, 0);
        for (int c = 0; c < 16; c++) {
            int sb = c & 1;
            if (c < 15) { issue(c + 1, sb ^ 1); CP_WAIT1(); } else { CP_WAIT0(); }
            {
                const char* stg = smem + GA_STG + sb * 16384;
                char* bh = smem + GA_BH + sb * 8704;
#pragma unroll
                for (int i = 0; i < 4; i++) {
                    int idx = i * 256 + tid;
                    int r = idx >> 5, cc = idx & 31;
                    float4 f = *(const float4*)(stg + r * 512 + cc * 16);
                    uint2 hv = make_uint2(
                        pkh(__float2half_rn(f.x), __float2half_rn(f.y)),
                        pkh(__float2half_rn(f.z), __float2half_rn(f.w)));
                    *(uint2*)(bh + r * LDB + cc * 8) = hv;
                }
            }
            __syncthreads();

            uint32_t sA = sbase + GA_A + sb * 10240;
            uint32_t sBH = sbase + GA_BH + sb * 8704;
#pragma unroll
            for (int ks = 0; ks < 2; ks++) {
                uint32_t ah[2][4];
#pragma unroll
                for (int mf = 0; mf < 2; mf++) {
                    uint32_t roff = (wm * 32 + mf * 16 + lr + (lg & 1) * 8) * LDR
                                  + (ks * 16 + (lg >> 1) * 8) * 2;
                    LDMATRIX_X4(ah[mf][0], ah[mf][1], ah[mf][2], ah[mf][3], sA + roff);
                }
                uint32_t trow = ks * 16 + ((lane >> 3) & 1) * 8 + lr;
                uint32_t bh[8][2];
#pragma unroll
                for (int np = 0; np < 4; np++) {
                    uint32_t tcol = wn * 64 + np * 16 + ((lane >> 4) & 1) * 8;
                    uint32_t r0, r1, r2, r3;
                    LDMATRIX_X4_T(r0, r1, r2, r3, sBH + trow * LDB + tcol * 2);
                    bh[np * 2][0] = r0; bh[np * 2][1] = r1;
                    bh[np * 2 + 1][0] = r2; bh[np * 2 + 1][1] = r3;
                }
#pragma unroll
                for (int mf = 0; mf < 2; mf++)
#pragma unroll
                    for (int nf = 0; nf < 8; nf++)
                        MMA16816(acc[mf][nf], ah[mf][0], ah[mf][1], ah[mf][2], ah[mf][3],
                                 bh[nf][0], bh[nf][1]);
            }
            __syncthreads();
        }

        char* st = smem;
#pragma unroll
        for (int mf = 0; mf < 2; mf++) {
            int row_l = wm * 32 + mf * 16 + (lane >> 2);
            int row = m0 + row_l;
            float bv0 = g_ball[row], bv1 = g_ball[row + 8];
            __half* op0 = g_vh + (size_t)b * CCH * HWV + (size_t)row * HWV
                        + n0 + wn * 64 + (lane & 3) * 2;
            __half* op1 = op0 + (size_t)8 * HWV;
#pragma unroll
            for (int nf = 0; nf < 8; nf++) {
                int n = wn * 64 + nf * 8 + (lane & 3) * 2;
                __half h00 = __float2half_rn(acc[mf][nf][0] + bv0);
                __half h01 = __float2half_rn(acc[mf][nf][1] + bv0);
                __half h10 = __float2half_rn(acc[mf][nf][2] + bv1);
                __half h11 = __float2half_rn(acc[mf][nf][3] + bv1);
                *(__half2*)(op0 + nf * 8) = __halves2half2(h00, h01);
                *(__half2*)(op1 + nf * 8) = __halves2half2(h10, h11);
                *(__half*)(st + n * 272 + row_l * 2)             = h00;
                *(__half*)(st + (n + 1) * 272 + row_l * 2)       = h01;
                *(__half*)(st + n * 272 + (row_l + 8) * 2)       = h10;
                *(__half*)(st + (n + 1) * 272 + (row_l + 8) * 2) = h11;
            }
        }
        __syncthreads();
#pragma unroll
        for (int i = 0; i < 8; i++) {
            int idx = i * 256 + tid;
            int w = idx >> 4, seg = idx & 15;
            *(uint4*)(g_vT + ((((size_t)b * WW + w) * HH + hfix) * CCH) + mt * 128 + seg * 8)
                = *(const uint4*)(st + w * 272 + seg * 16);
        }
    } else {
        int m0 = 512 + (mt - 4) * 64;
        int wm = wid & 1, wn = wid >> 1;
        const __half* Ahb = g_wall + (size_t)m0 * CCH;

        float acc[2][4][4];
#pragma unroll
        for (int i = 0; i < 2; i++)
#pragma unroll
            for (int j = 0; j < 4; j++)
#pragma unroll
                for (int k = 0; k < 4; k++) acc[i][j][k] = 0.f;

        auto issue = [&](int c, int sb) {
            int kc0 = c * 32;
            {
                int r = tid >> 2, seg = tid & 3;
                CP_ASYNC16(sbase + GA_A + sb * 10240 + r * LDR + seg * 16,
                           Ahb + (size_t)r * CCH + kc0 + seg * 8);
            }
#pragma unroll
            for (int i = 0; i < 4; i++) {
                int idx = i * 256 + tid;
                int r = idx >> 5, seg = idx & 31;
                CP_ASYNC16(sbase + GA_STG + sb * 16384 + r * 512 + seg * 16,
                           Xb + (size_t)(kc0 + r) * HWV + seg * 4);
            }
            CP_COMMIT();
        };

        issue(0, 0);
        for (int c = 0; c < 16; c++) {
            int sb = c & 1;
            if (c < 15) { issue(c + 1, sb ^ 1); CP_WAIT1(); } else { CP_WAIT0(); }
            {
                const char* stg = smem + GA_STG + sb * 16384;
                char* bh = smem + GA_BH + sb * 8704;
#pragma unroll
                for (int i = 0; i < 4; i++) {
                    int idx = i * 256 + tid;
                    int r = idx >> 5, cc = idx & 31;
                    float4 f = *(const float4*)(stg + r * 512 + cc * 16);
                    uint2 hv = make_uint2(
                        pkh(__float2half_rn(f.x), __float2half_rn(f.y)),
                        pkh(__float2half_rn(f.z), __float2half_rn(f.w)));
                    *(uint2*)(bh + r * LDB + cc * 8) = hv;
                }
            }
            __syncthreads();

            uint32_t sA = sbase + GA_A + sb * 10240;
            uint32_t sBH = sbase + GA_BH + sb * 8704;
#pragma unroll
            for (int ks = 0; ks < 2; ks++) {
                uint32_t ah[2][4];
#pragma unroll
                for (int mf = 0; mf < 2; mf++) {
                    uint32_t roff = (wm * 32 + mf * 16 + lr + (lg & 1) * 8) * LDR
                                  + (ks * 16 + (lg >> 1) * 8) * 2;
                    LDMATRIX_X4(ah[mf][0], ah[mf][1], ah[mf][2], ah[mf][3], sA + roff);
                }
                uint32_t trow = ks * 16 + ((lane >> 3) & 1) * 8 + lr;
                uint32_t bh[4][2];
#pragma unroll
                for (int np = 0; np < 2; np++) {
                    uint32_t tcol = wn * 32 + np * 16 + ((lane >> 4) & 1) * 8;
                    uint32_t r0, r1, r2, r3;
                    LDMATRIX_X4_T(r0, r1, r2, r3, sBH + trow * LDB + tcol * 2);
                    bh[np * 2][0] = r0; bh[np * 2][1] = r1;
                    bh[np * 2 + 1][0] = r2; bh[np * 2 + 1][1] = r3;
                }
#pragma unroll
                for (int mf = 0; mf < 2; mf++)
#pragma unroll
                    for (int nf = 0; nf < 4; nf++)
                        MMA16816(acc[mf][nf], ah[mf][0], ah[mf][1], ah[mf][2], ah[mf][3],
                                 bh[nf][0], bh[nf][1]);
            }
            __syncthreads();
        }

        char* st = smem;
#pragma unroll
        for (int mf = 0; mf < 2; mf++) {
            int row_l = wm * 32 + mf * 16 + (lane >> 2);
            float bv0 = g_ball[m0 + row_l], bv1 = g_ball[m0 + row_l + 8];
#pragma unroll
            for (int nf = 0; nf < 4; nf++) {
                int n = wn * 32 + nf * 8 + (lane & 3) * 2;
                *(__half*)(st + n * PTA + row_l * 2)             = __float2half_rn(acc[mf][nf][0] + bv0);
                *(__half*)(st + (n + 1) * PTA + row_l * 2)       = __float2half_rn(acc[mf][nf][1] + bv0);
                *(__half*)(st + n * PTA + (row_l + 8) * 2)       = __float2half_rn(acc[mf][nf][2] + bv1);
                *(__half*)(st + (n + 1) * PTA + (row_l + 8) * 2) = __float2half_rn(acc[mf][nf][3] + bv1);
            }
        }
        __syncthreads();
        __half* ta = (mt == 4) ? g_kTa : g_qTa;
        __half* tb = (mt == 4) ? g_kTb : g_qTb;
#pragma unroll
        for (int i = 0; i < 4; i++) {
            int idx = i * 256 + tid;
            int w = idx >> 3, seg = idx & 7;
            uint4 v = *(const uint4*)(st + w * PTA + seg * 16);
            *(uint4*)(ta + (((size_t)b * WW + w) * HH + hfix) * C8 + seg * 8) = v;
            *(uint4*)(tb + (((size_t)b * HH + hfix) * WW + w) * C8 + seg * 8) = v;
        }
    }
}

// ---------------- merged energy kernel ----------------------------------------
__global__ void __launch_bounds__(256) energy_all_kernel() {
    __shared__ __align__(16) char smh[2 * 128 * PTA];
    uint32_t sA = smem_u32(smh);
    uint32_t sB = sA + 128 * PTA;
    int tid = threadIdx.x, wid = tid >> 5, lane = tid & 31;
    int f = blockIdx.x, b = blockIdx.y;
    bool isH = (blockIdx.z == 0);
    int wm = wid & 3, wn = wid >> 2;

    const __half* qsrc;
    const __half* ksrc;
    __half* obase;
    if (isH) {
        qsrc = g_qTa + ((size_t)(b * WW + f)) * HH * C8;
        ksrc = g_kTa + ((size_t)(b * WW + f)) * HH * C8;
        obase = g_eH + (((size_t)b * WW + f) * HH) * 128;
    } else {
        qsrc = g_qTb + ((size_t)(b * HH + f)) * WW * C8;
        ksrc = g_kTb + ((size_t)(b * HH + f)) * WW * C8;
        obase = g_eW + (((size_t)b * HH + f) * WW) * 128;
    }
#pragma unroll
    for (int i = 0; i < 4; i++) {
        int idx = i * 256 + tid;
        int r = idx >> 3, seg = idx & 7;
        CP_ASYNC16(sA + r * PTA + seg * 16, qsrc + (size_t)r * C8 + seg * 8);
        CP_ASYNC16(sB + r * PTA + seg * 16, ksrc + (size_t)r * C8 + seg * 8);
    }
    CP_COMMIT(); CP_WAIT0();
    __syncthreads();

    float acc[2][8][4];
#pragma unroll
    for (int i = 0; i < 2; i++)
#pragma unroll
        for (int j = 0; j < 8; j++)
#pragma unroll
            for (int k = 0; k < 4; k++) acc[i][j][k] = 0.f;

    int lg = lane >> 3, lr = lane & 7;
#pragma unroll
    for (int kk = 0; kk < 4; kk++) {
        uint32_t a[2][4];
#pragma unroll
        for (int mf = 0; mf < 2; mf++) {
            uint32_t roff = (wm * 32 + mf * 16 + lr + (lg & 1) * 8) * PTA
                          + (kk * 16 + (lg >> 1) * 8) * 2;
            LDMATRIX_X4(a[mf][0], a[mf][1], a[mf][2], a[mf][3], sA + roff);
        }
        uint32_t bf[8][2];
#pragma unroll
        for (int np = 0; np < 4; np++) {
            uint32_t roff = (wn * 64 + np * 16 + (lg >> 1) * 8 + lr) * PTA
                          + (kk * 16 + (lg & 1) * 8) * 2;
            uint32_t r0, r1, r2, r3;
            LDMATRIX_X4(r0, r1, r2, r3, sB + roff);
            bf[np * 2][0] = r0; bf[np * 2][1] = r1;
            bf[np * 2 + 1][0] = r2; bf[np * 2 + 1][1] = r3;
        }
#pragma unroll
        for (int mf = 0; mf < 2; mf++)
#pragma unroll
            for (int nf = 0; nf < 8; nf++)
                MMA16816(acc[mf][nf], a[mf][0], a[mf][1], a[mf][2], a[mf][3],
                         bf[nf][0], bf[nf][1]);
    }
#pragma unroll
    for (int mf = 0; mf < 2; mf++) {
        int m0 = wm * 32 + mf * 16 + (lane >> 2);
        int m1 = m0 + 8;
#pragma unroll
        for (int nf = 0; nf < 8; nf++) {
            int j0 = wn * 64 + nf * 8 + (lane & 3) * 2;
            float v00 = acc[mf][nf][0], v01 = acc[mf][nf][1];
            float v10 = acc[mf][nf][2], v11 = acc[mf][nf][3];
            if (isH) {
                if (j0 == m0)     v00 = -30000.f;
                if (j0 + 1 == m0) v01 = -30000.f;
                if (j0 == m1)     v10 = -30000.f;
                if (j0 + 1 == m1) v11 = -30000.f;
            }
            *(__half2*)(obase + (size_t)m0 * 128 + j0) = __floats2half2_rn(v00, v01);
            *(__half2*)(obase + (size_t)m1 * 128 + j0) = __floats2half2_rn(v10, v11);
        }
    }
}

// ---------------- single-pass softmax (half2 vectorized) -----------------------
__global__ void softmax_apply_kernel() {
    int row  = blockIdx.x * 8 + (threadIdx.x >> 5);
    int lane = threadIdx.x & 31;
    int b = row >> 14, h = (row >> 7) & 127, w = row & 127;
    __half2* pH = (__half2*)(g_eH + (((size_t)b * WW + w) * HH + h) * 128);
    __half2* pW = (__half2*)(g_eW + (size_t)row * 128);
    float2 v[4];
    float m = -CUDART_INF_F;
#pragma unroll
    for (int i = 0; i < 2; i++) {
        v[i] = __half22float2(pH[lane + 32 * i]);
        m = fmaxf(m, fmaxf(v[i].x, v[i].y));
    }
#pragma unroll
    for (int i = 2; i < 4; i++) {
        v[i] = __half22float2(pW[lane + 32 * (i - 2)]);
        m = fmaxf(m, fmaxf(v[i].x, v[i].y));
    }
#pragma unroll
    for (int o = 16; o > 0; o >>= 1) m = fmaxf(m, __shfl_xor_sync(0xffffffffu, m, o));
    float s = 0.f;
#pragma unroll
    for (int i = 0; i < 4; i++) {
        v[i].x = fast_exp(v[i].x - m);
        v[i].y = fast_exp(v[i].y - m);
        s += v[i].x + v[i].y;
    }
#pragma unroll
    for (int o = 16; o > 0; o >>= 1) s += __shfl_xor_sync(0xffffffffu, s, o);
    float inv = 1.0f / s;
#pragma unroll
    for (int i = 0; i < 2; i++)
        pH[lane + 32 * i] = __floats2half2_rn(v[i].x * inv, v[i].y * inv);
#pragma unroll
    for (int i = 2; i < 4; i++)
        pW[lane + 32 * (i - 2)] = __floats2half2_rn(v[i].x * inv, v[i].y * inv);
}

// ---------------- attn out: 4 ct per block with prefetch overlap ---------------
#define AT_A   0            // 2 x 34816
#define AT_B   69632        // 34816
#define AT_SM  104448       // 2 CTAs/SM: 2 x 104448 <= 228KB

__global__ void __launch_bounds__(256) attn_all_kernel() {
    extern __shared__ char smem[];
    uint32_t sbase = smem_u32(smem);
    int tid = threadIdx.x, wid = tid >> 5, lane = tid & 31;
    int f = blockIdx.x, b = blockIdx.y;
    bool isH = (blockIdx.z == 0);
    int wm = wid & 3, wn = wid >> 2;

    const __half* Ab;
    const __half* Bm;
    __half* out;
    if (isH) {
        Ab = g_vT + ((size_t)(b * WW + f)) * HH * CCH;
        out = g_s1h; Bm = g_eH;
    } else {
        Ab = g_vh + (size_t)b * CCH * HWV + (size_t)f * WW;
        out = g_s2h; Bm = g_eW;
    }
    const __half* Bc = Bm + ((size_t)b * 128 + f) * 16384;

    auto issueA = [&](int ct, int buf) {
#pragma unroll
        for (int i = 0; i < 8; i++) {
            int idx = i * 256 + tid;
            int r = idx >> 4, seg = idx & 15;
            const __half* src = isH
                ? Ab + (size_t)r * CCH + ct * 128 + seg * 8
                : Ab + (size_t)(ct * 128 + r) * HWV + seg * 8;
            CP_ASYNC16(sbase + AT_A + buf * 34816 + r * LDT + seg * 16, src);
        }
        CP_COMMIT();
    };

    issueA(0, 0);
#pragma unroll
    for (int i = 0; i < 8; i++) {
        int idx = i * 256 + tid;
        int r = idx >> 4, seg = idx & 15;
        CP_ASYNC16(sbase + AT_B + r * LDT + seg * 16, Bc + (size_t)r * 128 + seg * 8);
    }
    CP_COMMIT(); CP_WAIT0();
    __syncthreads();

    int lg = lane >> 3, lr = lane & 7;
    uint32_t sB = sbase + AT_B;

    for (int ct = 0; ct < 4; ct++) {
        int buf = ct & 1;
        if (ct < 3) issueA(ct + 1, buf ^ 1);   // overlap next A load with MMA

        float acc[2][8][4];
#pragma unroll
        for (int i = 0; i < 2; i++)
#pragma unroll
            for (int j = 0; j < 8; j++)
#pragma unroll
                for (int k = 0; k < 4; k++) acc[i][j][k] = 0.f;

        uint32_t sA = sbase + AT_A + buf * 34816;
#pragma unroll
        for (int kk = 0; kk < 8; kk++) {
            uint32_t a[2][4];
            if (isH) {
#pragma unroll
                for (int mf = 0; mf < 2; mf++) {
                    uint32_t krow = kk * 16 + ((lane >> 4) & 1) * 8 + lr;
                    uint32_t mcol = wm * 32 + mf * 16 + ((lane >> 3) & 1) * 8;
                    LDMATRIX_X4_T(a[mf][0], a[mf][1], a[mf][2], a[mf][3],
                                  sA + krow * LDT + mcol * 2);
                }
            } else {
#pragma unroll
                for (int mf = 0; mf < 2; mf++) {
                    uint32_t roff = (wm * 32 + mf * 16 + lr + (lg & 1) * 8) * LDT
                                  + (kk * 16 + (lg >> 1) * 8) * 2;
                    LDMATRIX_X4(a[mf][0], a[mf][1], a[mf][2], a[mf][3], sA + roff);
                }
            }
            uint32_t bf[8][2];
#pragma unroll
            for (int np = 0; np < 4; np++) {
                uint32_t roff = (wn * 64 + np * 16 + (lg >> 1) * 8 + lr) * LDT
                              + (kk * 16 + (lg & 1) * 8) * 2;
                uint32_t r0, r1, r2, r3;
                LDMATRIX_X4(r0, r1, r2, r3, sB + roff);
                bf[np * 2][0] = r0; bf[np * 2][1] = r1;
                bf[np * 2 + 1][0] = r2; bf[np * 2 + 1][1] = r3;
            }
#pragma unroll
            for (int mf = 0; mf < 2; mf++)
#pragma unroll
                for (int nf = 0; nf < 8; nf++)
                    MMA16816(acc[mf][nf], a[mf][0], a[mf][1], a[mf][2], a[mf][3],
                             bf[nf][0], bf[nf][1]);
        }

        __half* oc = out + (size_t)b * CCH * HWV + (size_t)f * 128
                   + (size_t)ct * 128 * HWV;
#pragma unroll
        for (int mf = 0; mf < 2; mf++) {
            int row = wm * 32 + mf * 16 + (lane >> 2);
            __half* op0 = oc + (size_t)row * HWV + wn * 64 + (lane & 3) * 2;
            __half* op1 = op0 + (size_t)8 * HWV;
#pragma unroll
            for (int nf = 0; nf < 8; nf++) {
                *(__half2*)(op0 + nf * 8) = __floats2half2_rn(acc[mf][nf][0], acc[mf][nf][1]);
                *(__half2*)(op1 + nf * 8) = __floats2half2_rn(acc[mf][nf][2], acc[mf][nf][3]);
            }
        }
        if (ct < 3) { CP_WAIT0(); __syncthreads(); }
    }
}

// ---------------- combine (64x64 half2 tiles) ---------------------------------
__global__ void combine_kernel(float* __restrict__ out,
                               const float* __restrict__ xe,
                               const float* __restrict__ xq,
                               const float* __restrict__ g1p,
                               const float* __restrict__ g2p) {
    __shared__ __half2 sm[64][33];
    int bc = blockIdx.z;
    int w0 = blockIdx.x * 64, h0 = blockIdx.y * 64;
    int tx = threadIdx.x, ty = threadIdx.y;
    size_t base = (size_t)bc * HWV;
    const __half* s1 = g_s1h + base;
#pragma unroll
    for (int r = 0; r < 4; r++) {
        int wp = ty + r * 8;
        int w = w0 + 2 * wp;
        __half2 a = *(const __half2*)(s1 + (size_t)w * HH + h0 + 2 * tx);
        __half2 bq2 = *(const __half2*)(s1 + (size_t)(w + 1) * HH + h0 + 2 * tx);
        sm[2 * tx][wp]     = __halves2half2(__low2half(a),  __low2half(bq2));
        sm[2 * tx + 1][wp] = __halves2half2(__high2half(a), __high2half(bq2));
    }
    __syncthreads();
    float gam1 = g1p[0], gam2 = g2p[0];
#pragma unroll
    for (int r = 0; r < 8; r++) {
        int hl = ty + r * 8;
        int h = h0 + hl;
        size_t idx = base + (size_t)h * WW + w0 + 2 * tx;
        __half2 s1v = sm[hl][tx];
        __half2 s2v = *(const __half2*)(g_s2h + idx);
        float t0 = __low2float(s1v)  + __low2float(s2v)  + 2.0f;
        float t1 = __high2float(s1v) + __high2float(s2v) + 2.0f;
        float2 xev = *(const float2*)(xe + idx);
        float2 xqv = *(const float2*)(xq + idx);
        *(float2*)(out + idx) = make_float2(fmaf(gam1, t0, xev.x), fmaf(gam1, t1, xev.y));
        *(float2*)(out + NTOT + idx) = make_float2(fmaf(gam2, t0, xqv.x), fmaf(gam2, t1, xqv.y));
    }
}

// ---------------- launch ---------------------------------------------------------
extern "C" void kernel_launch(void* const* d_in, const int* in_sizes, int n_in,
                              void* d_out, int out_size) {
    const float* xe = (const float*)d_in[0];
    const float* xq = (const float*)d_in[1];
    const float* Wq = (const float*)d_in[2];
    const float* bq = (const float*)d_in[3];
    const float* Wk = (const float*)d_in[4];
    const float* bk = (const float*)d_in[5];
    const float* Wv = (const float*)d_in[6];
    const float* bv = (const float*)d_in[7];
    const float* g1 = (const float*)d_in[8];
    const float* g2 = (const float*)d_in[9];
    float* out = (float*)d_out;

    cudaFuncSetAttribute(gemm_all_kernel,
                         cudaFuncAttributeMaxDynamicSharedMemorySize, GA_SM);
    cudaFuncSetAttribute(attn_all_kernel,
                         cudaFuncAttributeMaxDynamicSharedMemorySize, AT_SM);

    // 1. weight/bias prep
    prep_kernel<<<(PREP_N + 255) / 256, 256>>>(Wq, Wv, Wk, bv, bk, bq);

    // 2. projections (2-stage pipeline, 2 CTAs/SM)
    gemm_all_kernel<<<dim3(6, HWV / 128, BB), 256, GA_SM>>>(xe, xq);

    // 3. both energies
    energy_all_kernel<<<dim3(128, BB, 2), 256>>>();

    // 4. single-pass softmax (half2 vectorized)
    softmax_apply_kernel<<<(BB * HH * WW) / 8, 256>>>();

    // 5. attention outputs (4 ct per block, prefetch-overlapped, 2 CTAs/SM)
    attn_all_kernel<<<dim3(128, BB, 2), 256, AT_SM>>>();

    // 6. combine
    combine_kernel<<<dim3(2, 2, BB * CCH), dim3(32, 8)>>>(out, xe, xq, g1, g2);
}